// round 13
// baseline (speedup 1.0000x reference)
#include <cuda_runtime.h>
#include <cuda_fp16.h>
#include <cstdint>

#define N_MAX 100000
#define N_PAD 100096
#define E_MAX 400000

// ---------------- scratch ---------------------------------------------------
__device__ __align__(16) __half g_a1[(size_t)N_PAD * 256];   // [agg1|x] fp16
__device__ __align__(16) __half g_t2[(size_t)N_MAX * 128];   // [t | o2] fp16
__device__ __align__(16) __half g_W1[256 * 256];             // [n][k]
__device__ __align__(16) __half g_W2[128 * 256];             // [n][k], n=[W2l|W2r]
__device__ int g_src[E_MAX], g_dst[E_MAX];
__device__ int g_cnt[N_MAX];            // zeroed by scan for next replay
__device__ int g_rowptr[N_MAX + 1], g_cursor[N_MAX], g_esrc[E_MAX];
__device__ volatile int g_flag[256];    // lookback status; zeroed by fill for next replay
__device__ volatile int g_bsum[256];
__device__ volatile int g_bpre[256];

// ---------------- helpers ---------------------------------------------------
__device__ __forceinline__ uint32_t smem_u32(const void* p) {
    uint32_t a;
    asm("{ .reg .u64 t; cvta.to.shared.u64 t, %1; cvt.u32.u64 %0, t; }" : "=r"(a) : "l"(p));
    return a;
}

__device__ __forceinline__ void cp16(uint32_t dst, const void* src) {
    asm volatile("cp.async.cg.shared.global [%0], [%1], 16;" :: "r"(dst), "l"(src) : "memory");
}
__device__ __forceinline__ void cp_commit() {
    asm volatile("cp.async.commit_group;" ::: "memory");
}
__device__ __forceinline__ void cp_wait0() {
    asm volatile("cp.async.wait_group 0;" ::: "memory");
}

__device__ __forceinline__ void ldsm_x4(uint32_t& r0, uint32_t& r1, uint32_t& r2, uint32_t& r3,
                                        uint32_t addr) {
    asm volatile("ldmatrix.sync.aligned.m8n8.x4.shared.b16 {%0,%1,%2,%3}, [%4];"
                 : "=r"(r0), "=r"(r1), "=r"(r2), "=r"(r3) : "r"(addr));
}

__device__ __forceinline__ void mma_f16(float* c, const uint32_t* a, uint32_t b0, uint32_t b1) {
    asm volatile(
        "mma.sync.aligned.m16n8k16.row.col.f32.f16.f16.f32 "
        "{%0,%1,%2,%3}, {%4,%5,%6,%7}, {%8,%9}, {%0,%1,%2,%3};"
        : "+f"(c[0]), "+f"(c[1]), "+f"(c[2]), "+f"(c[3])
        : "r"(a[0]), "r"(a[1]), "r"(a[2]), "r"(a[3]), "r"(b0), "r"(b1));
}

// ---------------- L1: convert edges (int32) + histogram + fp16 conversions ----
__global__ void prep_kernel(const int* __restrict__ ei, int E, int Nn,
                            const float* __restrict__ W1l, const float* __restrict__ W1r,
                            const float* __restrict__ W2l, const float* __restrict__ W2r,
                            const float* __restrict__ x) {
    const int EB = ((E + 255) / 256) * 256;
    int gid = blockIdx.x * 256 + threadIdx.x;
    if (gid < EB) {
        int e = gid;
        if (e < E) {
            int s = ei[e], d = ei[E + e];
            if (s < 0) s = 0; if (s >= Nn) s = Nn - 1;
            if (d < 0) d = 0; if (d >= Nn) d = Nn - 1;
            g_src[e] = s;
            g_dst[e] = d;
            atomicAdd(&g_cnt[d], 1);
        }
        return;
    }
    int g = gid - EB;
    if (g < 65536) {                         // W1 transposed
        int n = g & 255, k = g >> 8;
        float v = (k < 128) ? W1l[(size_t)k * 256 + n] : W1r[(size_t)(k - 128) * 256 + n];
        g_W1[n * 256 + k] = __float2half_rn(v);
    } else if (g < 98304) {                  // W2, n = [W2l|W2r]
        int q = g - 65536;
        int n = q & 127, k = q >> 7;
        float v = (n < 64) ? W2l[(size_t)k * 64 + n] : W2r[(size_t)k * 64 + (n - 64)];
        g_W2[n * 256 + k] = __float2half_rn(v);
    } else {                                 // x -> fp16, cols 128..255 of A1
        int q = g - 98304;
        if (q >= Nn * 32) return;
        int node = q >> 5;
        int c = (q & 31) * 4;
        float4 v = *(const float4*)(x + (size_t)node * 128 + c);
        __half2 p0 = __floats2half2_rn(v.x, v.y);
        __half2 p1 = __floats2half2_rn(v.z, v.w);
        *(uint2*)(g_a1 + (size_t)node * 256 + 128 + c) =
            make_uint2(*(uint32_t*)&p0, *(uint32_t*)&p1);
    }
}

// ---------------- L2: single-kernel decoupled-lookback scan -------------------
__global__ void scan_kernel(int Nn, int E) {
    __shared__ int s[512];
    __shared__ int s_off;
    const int bid = blockIdx.x;
    const int i = bid * 512 + threadIdx.x;
    int v = (i < Nn) ? g_cnt[i] : 0;
    s[threadIdx.x] = v;
    __syncthreads();
#pragma unroll
    for (int off = 1; off < 512; off <<= 1) {
        int t = (threadIdx.x >= off) ? s[threadIdx.x - off] : 0;
        __syncthreads();
        s[threadIdx.x] += t;
        __syncthreads();
    }
    if (threadIdx.x == 0) {
        int total = s[511];
        g_bsum[bid] = total;
        __threadfence();
        g_flag[bid] = 1;
        int excl = 0;
        for (int j = bid - 1; j >= 0; j--) {
            int f;
            do { f = g_flag[j]; } while (f == 0);
            if (f == 2) { excl += g_bpre[j]; break; }
            excl += g_bsum[j];
        }
        g_bpre[bid] = excl + total;
        __threadfence();
        g_flag[bid] = 2;
        s_off = excl;
    }
    __syncthreads();
    if (i < Nn) {
        int r = s[threadIdx.x] - v + s_off;
        g_rowptr[i] = r;
        g_cursor[i] = r;
        g_cnt[i] = 0;                        // ready for next replay
    }
    if (i == 0) g_rowptr[Nn] = E;
}

// ---------------- L3: fill CSR (+ reset lookback flags) -----------------------
__global__ void fill_kernel(int E) {
    int e = blockIdx.x * blockDim.x + threadIdx.x;
    if (e < 256) g_flag[e] = 0;
    if (e < E) {
        int pos = atomicAdd(&g_cursor[g_dst[e]], 1);
        g_esrc[pos] = g_src[e];
    }
}

// ---------------- L4: agg1 — 2 nodes/warp, uint4 loads, fp32 accumulate -------
__global__ void agg1_kernel(int Nn) {
    int gw = (blockIdx.x * blockDim.x + threadIdx.x) >> 5;
    int lane = threadIdx.x & 31;
    int node = gw * 2 + (lane >> 4);
    int hl = lane & 15;
    if (node >= Nn) return;
    int s0 = g_rowptr[node], s1 = g_rowptr[node + 1];
    float acc[8] = {0.f, 0.f, 0.f, 0.f, 0.f, 0.f, 0.f, 0.f};
    for (int e = s0; e < s1; e++) {
        int src = g_esrc[e];
        uint4 u = *(const uint4*)(g_a1 + (size_t)src * 256 + 128 + hl * 8);
        float2 f0 = __half22float2(*(__half2*)&u.x);
        float2 f1 = __half22float2(*(__half2*)&u.y);
        float2 f2 = __half22float2(*(__half2*)&u.z);
        float2 f3 = __half22float2(*(__half2*)&u.w);
        acc[0] += f0.x; acc[1] += f0.y; acc[2] += f1.x; acc[3] += f1.y;
        acc[4] += f2.x; acc[5] += f2.y; acc[6] += f3.x; acc[7] += f3.y;
    }
    float inv = 1.f / fmaxf((float)(s1 - s0), 1.f);
    __half2 p0 = __floats2half2_rn(acc[0] * inv, acc[1] * inv);
    __half2 p1 = __floats2half2_rn(acc[2] * inv, acc[3] * inv);
    __half2 p2 = __floats2half2_rn(acc[4] * inv, acc[5] * inv);
    __half2 p3 = __floats2half2_rn(acc[6] * inv, acc[7] * inv);
    uint4 o;
    o.x = *(uint32_t*)&p0; o.y = *(uint32_t*)&p1;
    o.z = *(uint32_t*)&p2; o.w = *(uint32_t*)&p3;
    *(uint4*)(g_a1 + (size_t)node * 256 + hl * 8) = o;
}

// ---------------- L5: FUSED GEMM1+GEMM2 ---------------------------------------
// Phase 1: h[128,256] = relu([agg1|x](tile) @ W1 + b1)  -> SMEM only
// Phase 2: t2[128,128] = h @ W2                          -> g_t2
#define ROWB 144
#define A_TB (128 * ROWB)          // 18432
#define B_TB (256 * ROWB)          // 36864
#define HROW 528                   // 256 fp16 + 16B pad
#define H_BYTES (128 * HROW)       // 67584
#define W2_OFF 110592              // after phase-1 buffers
#define SMEM_FUSED (W2_OFF + H_BYTES)   // 178176

__global__ __launch_bounds__(256, 1)
void fused_mma_kernel(const float* __restrict__ b1, int Nn) {
    extern __shared__ char sm[];
    const uint32_t smb = smem_u32(sm);
    const uint32_t Abuf[2] = { smb, smb + A_TB };
    const uint32_t Bbuf[2] = { smb + 2 * A_TB, smb + 2 * A_TB + B_TB };
    const uint32_t H = smb;                       // reuses phase-1 buffers
    const uint32_t W2S = smb + W2_OFF;

    const int tid = threadIdx.x;
    const int wid = tid >> 5;
    const int lane = tid & 31;
    const int m0 = blockIdx.x * 128;

    const int wm = (wid >> 2) * 64;
    const int lrow = lane & 15;
    const int lcol8 = (lane >> 4) * 8;

    // ---- W2 preload (whole 128x256 fp16 -> W2S, 528B rows) ----
    {
        int n = tid >> 1;
        int hf = tid & 1;
        const char* src = (const char*)(g_W2 + n * 256) + hf * 256;
        uint32_t dst = W2S + n * HROW + hf * 256;
#pragma unroll
        for (int j = 0; j < 16; j++) cp16(dst + j * 16, src + j * 16);
    }

    // ---- phase-1 tile loaders ----
    auto loadA = [&](uint32_t sA, int k0) {
        int row = tid >> 1;
        const char* src = (const char*)(g_a1 + (size_t)(m0 + row) * 256 + k0) + (tid & 1) * 64;
        uint32_t d = sA + row * ROWB + (tid & 1) * 64;
#pragma unroll
        for (int j = 0; j < 4; j++) cp16(d + j * 16, src + j * 16);
    };
    auto loadB = [&](uint32_t sB, int k0) {
        int row = tid;                     // 256 n-rows
        const char* src = (const char*)(g_W1 + (size_t)row * 256 + k0);
        uint32_t d = sB + row * ROWB;
#pragma unroll
        for (int j = 0; j < 8; j++) cp16(d + j * 16, src + j * 16);
    };

    float acc[4][8][4];
#pragma unroll
    for (int i = 0; i < 4; i++)
#pragma unroll
        for (int j = 0; j < 8; j++)
#pragma unroll
            for (int q = 0; q < 4; q++) acc[i][j][q] = 0.f;

    loadA(Abuf[0], 0);
    loadB(Bbuf[0], 0);
    cp_commit();
    cp_wait0();                            // also drains W2 preload
    __syncthreads();

    const int wn1 = (wid & 3) * 64;        // phase-1 warp covers 64 n-cols
    for (int s = 0; s < 4; s++) {
        int sn = s + 1;
        if (sn < 4) {
            loadA(Abuf[sn & 1], sn * 64);
            loadB(Bbuf[sn & 1], sn * 64);
            cp_commit();
        }
        uint32_t sA = Abuf[s & 1], sB = Bbuf[s & 1];
#pragma unroll
        for (int ks = 0; ks < 4; ks++) {
            int kb = ks * 16 + lcol8;
            uint32_t a[4][4], b[4][4];
#pragma unroll
            for (int mt = 0; mt < 4; mt++)
                ldsm_x4(a[mt][0], a[mt][1], a[mt][2], a[mt][3],
                        sA + (wm + mt * 16 + lrow) * ROWB + kb * 2);
#pragma unroll
            for (int p = 0; p < 4; p++)
                ldsm_x4(b[p][0], b[p][1], b[p][2], b[p][3],
                        sB + (wn1 + p * 16 + lrow) * ROWB + kb * 2);
#pragma unroll
            for (int mt = 0; mt < 4; mt++)
#pragma unroll
                for (int nt = 0; nt < 8; nt++)
                    mma_f16(acc[mt][nt], a[mt], b[nt >> 1][nt & 1], b[nt >> 1][(nt & 1) + 2]);
        }
        if (sn < 4) cp_wait0();
        __syncthreads();
    }
    __syncthreads();                       // phase-1 buffers dead; H may overwrite

    // ---- epilogue 1: bias + relu -> h in SMEM (fp16, 528B rows) ----
#pragma unroll
    for (int mt = 0; mt < 4; mt++) {
        int rl = wm + mt * 16 + (lane >> 2);
#pragma unroll
        for (int nt = 0; nt < 8; nt++) {
            int col = wn1 + nt * 8 + (lane & 3) * 2;
            float bb0 = __ldg(b1 + col), bb1 = __ldg(b1 + col + 1);
#pragma unroll
            for (int h = 0; h < 2; h++) {
                float v0 = fmaxf(acc[mt][nt][2 * h + 0] + bb0, 0.f);
                float v1 = fmaxf(acc[mt][nt][2 * h + 1] + bb1, 0.f);
                __half2 p = __floats2half2_rn(v0, v1);
                *(uint32_t*)(sm + (H - smb) + (rl + h * 8) * HROW + col * 2) = *(uint32_t*)&p;
            }
        }
    }
    __syncthreads();

    // ---- phase 2: t2 = h @ W2 (all SMEM) ----
    const int wn2 = (wid & 3) * 32;
#pragma unroll
    for (int i = 0; i < 4; i++)
#pragma unroll
        for (int j = 0; j < 4; j++)
#pragma unroll
            for (int q = 0; q < 4; q++) acc[i][j][q] = 0.f;

#pragma unroll
    for (int c = 0; c < 4; c++) {
#pragma unroll
        for (int ks = 0; ks < 4; ks++) {
            int kb = c * 64 + ks * 16 + lcol8;
            uint32_t a[4][4], b[2][4];
#pragma unroll
            for (int mt = 0; mt < 4; mt++)
                ldsm_x4(a[mt][0], a[mt][1], a[mt][2], a[mt][3],
                        H + (wm + mt * 16 + lrow) * HROW + kb * 2);
#pragma unroll
            for (int p = 0; p < 2; p++)
                ldsm_x4(b[p][0], b[p][1], b[p][2], b[p][3],
                        W2S + (wn2 + p * 16 + lrow) * HROW + kb * 2);
#pragma unroll
            for (int mt = 0; mt < 4; mt++)
#pragma unroll
                for (int nt = 0; nt < 4; nt++)
                    mma_f16(acc[mt][nt], a[mt], b[nt >> 1][nt & 1], b[nt >> 1][(nt & 1) + 2]);
        }
    }

    // ---- epilogue 2: write g_t2 ----
#pragma unroll
    for (int mt = 0; mt < 4; mt++) {
        int r0 = m0 + wm + mt * 16 + (lane >> 2);
#pragma unroll
        for (int nt = 0; nt < 4; nt++) {
            int colL = wn2 + nt * 8 + (lane & 3) * 2;
#pragma unroll
            for (int h = 0; h < 2; h++) {
                int r = r0 + h * 8;
                if (r < Nn) {
                    __half2 p = __floats2half2_rn(acc[mt][nt][2 * h + 0],
                                                  acc[mt][nt][2 * h + 1]);
                    *(uint32_t*)(g_t2 + (size_t)r * 128 + colL) = *(uint32_t*)&p;
                }
            }
        }
    }
}

// ---------------- L6: agg2 + final — 2 nodes/warp, fp32 accumulate ------------
__global__ void agg2_final_kernel(const float* __restrict__ b2,
                                  float* __restrict__ out, int Nn) {
    int gw = (blockIdx.x * blockDim.x + threadIdx.x) >> 5;
    int lane = threadIdx.x & 31;
    int node = gw * 2 + (lane >> 4);
    int hl = lane & 15;
    if (node >= Nn) return;
    int s0 = g_rowptr[node], s1 = g_rowptr[node + 1];
    float acc[4] = {0.f, 0.f, 0.f, 0.f};
    for (int e = s0; e < s1; e++) {
        int src = g_esrc[e];
        uint2 u = *(const uint2*)(g_t2 + (size_t)src * 128 + hl * 4);
        float2 f0 = __half22float2(*(__half2*)&u.x);
        float2 f1 = __half22float2(*(__half2*)&u.y);
        acc[0] += f0.x; acc[1] += f0.y; acc[2] += f1.x; acc[3] += f1.y;
    }
    float inv = 1.f / fmaxf((float)(s1 - s0), 1.f);
    uint2 uo = *(const uint2*)(g_t2 + (size_t)node * 128 + 64 + hl * 4);
    float2 o0 = __half22float2(*(__half2*)&uo.x);
    float2 o1 = __half22float2(*(__half2*)&uo.y);
    float4 bb = *(const float4*)(b2 + hl * 4);
    float4 v;
    v.x = acc[0] * inv + o0.x + bb.x;
    v.y = acc[1] * inv + o0.y + bb.y;
    v.z = acc[2] * inv + o1.x + bb.z;
    v.w = acc[3] * inv + o1.y + bb.w;
    *(float4*)(out + (size_t)node * 64 + hl * 4) = v;
}

// ---------------- launch --------------------------------------------------------
extern "C" void kernel_launch(void* const* d_in, const int* in_sizes, int n_in,
                              void* d_out, int out_size) {
    const float* x   = (const float*)d_in[0];
    const int*   ei  = (const int*)d_in[1];      // staged int32 (verified empirically)
    const float* W1l = (const float*)d_in[2];
    const float* b1  = (const float*)d_in[3];
    const float* W1r = (const float*)d_in[4];
    const float* W2l = (const float*)d_in[5];
    const float* b2  = (const float*)d_in[6];
    const float* W2r = (const float*)d_in[7];
    float*       out = (float*)d_out;

    const int Nn = in_sizes[0] / 128;
    const int E  = in_sizes[1] / 2;
    const int nb = (Nn + 511) / 512;

    cudaFuncSetAttribute(fused_mma_kernel,
                         cudaFuncAttributeMaxDynamicSharedMemorySize, SMEM_FUSED);

    const int EB = ((E + 255) / 256) * 256;
    const int prepThreads = EB + 98304 + Nn * 32;
    prep_kernel<<<(prepThreads + 255) / 256, 256>>>(ei, E, Nn, W1l, W1r, W2l, W2r, x);
    scan_kernel<<<nb, 512>>>(Nn, E);
    fill_kernel<<<(E + 255) / 256, 256>>>(E);
    agg1_kernel<<<(Nn * 16 + 255) / 256, 256>>>(Nn);

    fused_mma_kernel<<<(Nn + 127) / 128, 256, SMEM_FUSED>>>(b1, Nn);

    agg2_final_kernel<<<(Nn * 16 + 255) / 256, 256>>>(b2, out, Nn);
}

// round 14
// speedup vs baseline: 1.0066x; 1.0066x over previous
#include <cuda_runtime.h>
#include <cuda_fp16.h>
#include <cstdint>

#define N_MAX 100000
#define N_PAD 100096
#define E_MAX 400000

// ---------------- scratch ---------------------------------------------------
__device__ __align__(16) __half g_a1[(size_t)N_PAD * 256];   // [agg1|x] fp16
__device__ __align__(16) __half g_h [(size_t)N_PAD * 256];   // hidden fp16
__device__ __align__(16) __half g_t2[(size_t)N_MAX * 128];   // [t | o2] fp16
__device__ __align__(16) __half g_W1[256 * 256];             // [n][k]
__device__ __align__(16) __half g_W2[128 * 256];             // [n][k], n=[W2l|W2r]
__device__ int g_src[E_MAX], g_dst[E_MAX];
__device__ int g_cnt[N_MAX];            // zeroed by scan for next replay
__device__ int g_rowptr[N_MAX + 1], g_cursor[N_MAX], g_esrc[E_MAX];
__device__ volatile int g_flag[256];    // lookback status; zeroed by fill for next replay
__device__ volatile int g_bsum[256];
__device__ volatile int g_bpre[256];

// ---------------- helpers ---------------------------------------------------
__device__ __forceinline__ uint32_t smem_u32(const void* p) {
    uint32_t a;
    asm("{ .reg .u64 t; cvta.to.shared.u64 t, %1; cvt.u32.u64 %0, t; }" : "=r"(a) : "l"(p));
    return a;
}

__device__ __forceinline__ void cp16(uint32_t dst, const void* src) {
    asm volatile("cp.async.cg.shared.global [%0], [%1], 16;" :: "r"(dst), "l"(src) : "memory");
}
__device__ __forceinline__ void cp_commit() {
    asm volatile("cp.async.commit_group;" ::: "memory");
}
__device__ __forceinline__ void cp_wait0() {
    asm volatile("cp.async.wait_group 0;" ::: "memory");
}

__device__ __forceinline__ void ldsm_x4(uint32_t& r0, uint32_t& r1, uint32_t& r2, uint32_t& r3,
                                        uint32_t addr) {
    asm volatile("ldmatrix.sync.aligned.m8n8.x4.shared.b16 {%0,%1,%2,%3}, [%4];"
                 : "=r"(r0), "=r"(r1), "=r"(r2), "=r"(r3) : "r"(addr));
}

__device__ __forceinline__ void mma_f16(float* c, const uint32_t* a, uint32_t b0, uint32_t b1) {
    asm volatile(
        "mma.sync.aligned.m16n8k16.row.col.f32.f16.f16.f32 "
        "{%0,%1,%2,%3}, {%4,%5,%6,%7}, {%8,%9}, {%0,%1,%2,%3};"
        : "+f"(c[0]), "+f"(c[1]), "+f"(c[2]), "+f"(c[3])
        : "r"(a[0]), "r"(a[1]), "r"(a[2]), "r"(a[3]), "r"(b0), "r"(b1));
}

// ---------------- L1: convert edges (int32) + histogram + fp16 conversions ----
__global__ void prep_kernel(const int* __restrict__ ei, int E, int Nn,
                            const float* __restrict__ W1l, const float* __restrict__ W1r,
                            const float* __restrict__ W2l, const float* __restrict__ W2r,
                            const float* __restrict__ x) {
    const int EB = ((E + 255) / 256) * 256;
    int gid = blockIdx.x * 256 + threadIdx.x;
    if (gid < EB) {
        int e = gid;
        if (e < E) {
            int s = ei[e], d = ei[E + e];
            if (s < 0) s = 0; if (s >= Nn) s = Nn - 1;
            if (d < 0) d = 0; if (d >= Nn) d = Nn - 1;
            g_src[e] = s;
            g_dst[e] = d;
            atomicAdd(&g_cnt[d], 1);
        }
        return;
    }
    int g = gid - EB;
    if (g < 65536) {                         // W1 transposed
        int n = g & 255, k = g >> 8;
        float v = (k < 128) ? W1l[(size_t)k * 256 + n] : W1r[(size_t)(k - 128) * 256 + n];
        g_W1[n * 256 + k] = __float2half_rn(v);
    } else if (g < 98304) {                  // W2, n = [W2l|W2r]
        int q = g - 65536;
        int n = q & 127, k = q >> 7;
        float v = (n < 64) ? W2l[(size_t)k * 64 + n] : W2r[(size_t)k * 64 + (n - 64)];
        g_W2[n * 256 + k] = __float2half_rn(v);
    } else {                                 // x -> fp16, cols 128..255 of A1
        int q = g - 98304;
        if (q >= Nn * 32) return;
        int node = q >> 5;
        int c = (q & 31) * 4;
        float4 v = *(const float4*)(x + (size_t)node * 128 + c);
        __half2 p0 = __floats2half2_rn(v.x, v.y);
        __half2 p1 = __floats2half2_rn(v.z, v.w);
        *(uint2*)(g_a1 + (size_t)node * 256 + 128 + c) =
            make_uint2(*(uint32_t*)&p0, *(uint32_t*)&p1);
    }
}

// ---------------- L2: single-kernel decoupled-lookback scan -------------------
__global__ void scan_kernel(int Nn, int E) {
    __shared__ int s[512];
    __shared__ int s_off;
    const int bid = blockIdx.x;
    const int i = bid * 512 + threadIdx.x;
    int v = (i < Nn) ? g_cnt[i] : 0;
    s[threadIdx.x] = v;
    __syncthreads();
#pragma unroll
    for (int off = 1; off < 512; off <<= 1) {
        int t = (threadIdx.x >= off) ? s[threadIdx.x - off] : 0;
        __syncthreads();
        s[threadIdx.x] += t;
        __syncthreads();
    }
    if (threadIdx.x == 0) {
        int total = s[511];
        g_bsum[bid] = total;
        __threadfence();
        g_flag[bid] = 1;
        int excl = 0;
        for (int j = bid - 1; j >= 0; j--) {
            int f;
            do { f = g_flag[j]; } while (f == 0);
            if (f == 2) { excl += g_bpre[j]; break; }
            excl += g_bsum[j];
        }
        g_bpre[bid] = excl + total;
        __threadfence();
        g_flag[bid] = 2;
        s_off = excl;
    }
    __syncthreads();
    if (i < Nn) {
        int r = s[threadIdx.x] - v + s_off;
        g_rowptr[i] = r;
        g_cursor[i] = r;
        g_cnt[i] = 0;                        // ready for next replay
    }
    if (i == 0) g_rowptr[Nn] = E;
}

// ---------------- L3: fill CSR (+ reset lookback flags) -----------------------
__global__ void fill_kernel(int E) {
    int e = blockIdx.x * blockDim.x + threadIdx.x;
    if (e < 256) g_flag[e] = 0;
    if (e < E) {
        int pos = atomicAdd(&g_cursor[g_dst[e]], 1);
        g_esrc[pos] = g_src[e];
    }
}

// ---------------- L4: agg1 — 2 nodes/warp, 4-deep pipelined gather ------------
__global__ void agg1_kernel(int Nn) {
    int gw = (blockIdx.x * blockDim.x + threadIdx.x) >> 5;
    int lane = threadIdx.x & 31;
    int node = gw * 2 + (lane >> 4);
    int hl = lane & 15;
    if (node >= Nn) return;
    int s0 = g_rowptr[node], s1 = g_rowptr[node + 1];
    float acc[8] = {0.f, 0.f, 0.f, 0.f, 0.f, 0.f, 0.f, 0.f};
    const __half* base = g_a1 + 128 + hl * 8;

    int e = s0;
    for (; e + 3 < s1; e += 4) {
        int i0 = g_esrc[e], i1 = g_esrc[e + 1], i2 = g_esrc[e + 2], i3 = g_esrc[e + 3];
        uint4 u0 = *(const uint4*)(base + (size_t)i0 * 256);
        uint4 u1 = *(const uint4*)(base + (size_t)i1 * 256);
        uint4 u2 = *(const uint4*)(base + (size_t)i2 * 256);
        uint4 u3 = *(const uint4*)(base + (size_t)i3 * 256);
#define ACC8(U) do { \
        float2 f0 = __half22float2(*(__half2*)&(U).x); \
        float2 f1 = __half22float2(*(__half2*)&(U).y); \
        float2 f2 = __half22float2(*(__half2*)&(U).z); \
        float2 f3 = __half22float2(*(__half2*)&(U).w); \
        acc[0] += f0.x; acc[1] += f0.y; acc[2] += f1.x; acc[3] += f1.y; \
        acc[4] += f2.x; acc[5] += f2.y; acc[6] += f3.x; acc[7] += f3.y; } while (0)
        ACC8(u0); ACC8(u1); ACC8(u2); ACC8(u3);
    }
    for (; e < s1; e++) {
        int i0 = g_esrc[e];
        uint4 u0 = *(const uint4*)(base + (size_t)i0 * 256);
        ACC8(u0);
    }
#undef ACC8

    float inv = 1.f / fmaxf((float)(s1 - s0), 1.f);
    __half2 p0 = __floats2half2_rn(acc[0] * inv, acc[1] * inv);
    __half2 p1 = __floats2half2_rn(acc[2] * inv, acc[3] * inv);
    __half2 p2 = __floats2half2_rn(acc[4] * inv, acc[5] * inv);
    __half2 p3 = __floats2half2_rn(acc[6] * inv, acc[7] * inv);
    uint4 o;
    o.x = *(uint32_t*)&p0; o.y = *(uint32_t*)&p1;
    o.z = *(uint32_t*)&p2; o.w = *(uint32_t*)&p3;
    *(uint4*)(g_a1 + (size_t)node * 256 + hl * 8) = o;
}

// ---------------- L5/L6: HMMA fp16 GEMM ---------------------------------------
#define ROWB 144
#define TILE_BYTES (128 * ROWB)

__device__ __forceinline__ void load_one(uint32_t sT, const __half* __restrict__ T,
                                         int row0, int k0, int tid) {
    int row = tid >> 1;
    const char* src = (const char*)(T + (size_t)(row0 + row) * 256 + k0) + (tid & 1) * 64;
    uint32_t d = sT + row * ROWB + (tid & 1) * 64;
#pragma unroll
    for (int j = 0; j < 4; j++) cp16(d + j * 16, src + j * 16);
}

// MODE 1: D[.,256] = [agg1|x] @ W1 ; +b1, relu -> g_h (fp16)
// MODE 2: D[.,128] = h @ [W2l|W2r] ; fp16 -> g_t2 (t cols 0-63, o2 cols 64-127)
template <int MODE>
__global__ __launch_bounds__(256, 2)
void mma_kernel(const float* __restrict__ bias, int Nn) {
    extern __shared__ char sm[];
    const uint32_t smb = smem_u32(sm);
    const uint32_t Abuf[2] = { smb, smb + TILE_BYTES };
    const uint32_t Bbuf[2] = { smb + 2 * TILE_BYTES, smb + 3 * TILE_BYTES };

    const int tid = threadIdx.x;
    const int wid = tid >> 5;
    const int lane = tid & 31;
    const int m0 = blockIdx.x * 128;
    const int n0 = blockIdx.y * 128;

    const __half* A = (MODE == 1) ? g_a1 : g_h;
    const __half* B = (MODE == 1) ? g_W1 : g_W2;

    const int wm = (wid >> 2) * 64;
    const int wn = (wid & 3) * 32;
    const int lrow = lane & 15;
    const int lcol8 = (lane >> 4) * 8;

    float acc[4][4][4];
#pragma unroll
    for (int i = 0; i < 4; i++)
#pragma unroll
        for (int j = 0; j < 4; j++)
#pragma unroll
            for (int q = 0; q < 4; q++) acc[i][j][q] = 0.f;

    load_one(Abuf[0], A, m0, 0, tid);
    load_one(Bbuf[0], B, n0, 0, tid);
    cp_commit();
    cp_wait0();
    __syncthreads();

    for (int s = 0; s < 4; s++) {
        int sn = s + 1;
        if (sn < 4) {
            load_one(Abuf[sn & 1], A, m0, sn * 64, tid);
            load_one(Bbuf[sn & 1], B, n0, sn * 64, tid);
            cp_commit();
        }
        uint32_t sA = Abuf[s & 1], sB = Bbuf[s & 1];
#pragma unroll
        for (int ks = 0; ks < 4; ks++) {
            int kb = ks * 16 + lcol8;
            uint32_t a[4][4], b[2][4];
#pragma unroll
            for (int mt = 0; mt < 4; mt++)
                ldsm_x4(a[mt][0], a[mt][1], a[mt][2], a[mt][3],
                        sA + (wm + mt * 16 + lrow) * ROWB + kb * 2);
#pragma unroll
            for (int p = 0; p < 2; p++)
                ldsm_x4(b[p][0], b[p][1], b[p][2], b[p][3],
                        sB + (wn + p * 16 + lrow) * ROWB + kb * 2);
#pragma unroll
            for (int mt = 0; mt < 4; mt++)
#pragma unroll
                for (int nt = 0; nt < 4; nt++)
                    mma_f16(acc[mt][nt], a[mt], b[nt >> 1][nt & 1], b[nt >> 1][(nt & 1) + 2]);
        }
        if (sn < 4) cp_wait0();
        __syncthreads();
    }

#pragma unroll
    for (int mt = 0; mt < 4; mt++) {
        int r0 = m0 + wm + mt * 16 + (lane >> 2);
#pragma unroll
        for (int nt = 0; nt < 4; nt++) {
            int colL = wn + nt * 8 + (lane & 3) * 2;
            if (MODE == 1) {
                int col = n0 + colL;
                float bb0 = __ldg(bias + col), bb1 = __ldg(bias + col + 1);
#pragma unroll
                for (int h = 0; h < 2; h++) {
                    int r = r0 + h * 8;
                    if (r < Nn) {
                        float v0 = fmaxf(acc[mt][nt][2 * h + 0] + bb0, 0.f);
                        float v1 = fmaxf(acc[mt][nt][2 * h + 1] + bb1, 0.f);
                        __half2 p = __floats2half2_rn(v0, v1);
                        *(uint32_t*)(g_h + (size_t)r * 256 + col) = *(uint32_t*)&p;
                    }
                }
            } else {
#pragma unroll
                for (int h = 0; h < 2; h++) {
                    int r = r0 + h * 8;
                    if (r < Nn) {
                        __half2 p = __floats2half2_rn(acc[mt][nt][2 * h + 0],
                                                      acc[mt][nt][2 * h + 1]);
                        *(uint32_t*)(g_t2 + (size_t)r * 128 + colL) = *(uint32_t*)&p;
                    }
                }
            }
        }
    }
}

// ---------------- L7: agg2 + final — 2 nodes/warp, 4-deep pipelined gather ----
__global__ void agg2_final_kernel(const float* __restrict__ b2,
                                  float* __restrict__ out, int Nn) {
    int gw = (blockIdx.x * blockDim.x + threadIdx.x) >> 5;
    int lane = threadIdx.x & 31;
    int node = gw * 2 + (lane >> 4);
    int hl = lane & 15;
    if (node >= Nn) return;
    int s0 = g_rowptr[node], s1 = g_rowptr[node + 1];
    float acc[4] = {0.f, 0.f, 0.f, 0.f};
    const __half* base = g_t2 + hl * 4;

    int e = s0;
    for (; e + 3 < s1; e += 4) {
        int i0 = g_esrc[e], i1 = g_esrc[e + 1], i2 = g_esrc[e + 2], i3 = g_esrc[e + 3];
        uint2 u0 = *(const uint2*)(base + (size_t)i0 * 128);
        uint2 u1 = *(const uint2*)(base + (size_t)i1 * 128);
        uint2 u2 = *(const uint2*)(base + (size_t)i2 * 128);
        uint2 u3 = *(const uint2*)(base + (size_t)i3 * 128);
#define ACC4(U) do { \
        float2 f0 = __half22float2(*(__half2*)&(U).x); \
        float2 f1 = __half22float2(*(__half2*)&(U).y); \
        acc[0] += f0.x; acc[1] += f0.y; acc[2] += f1.x; acc[3] += f1.y; } while (0)
        ACC4(u0); ACC4(u1); ACC4(u2); ACC4(u3);
    }
    for (; e < s1; e++) {
        int i0 = g_esrc[e];
        uint2 u0 = *(const uint2*)(base + (size_t)i0 * 128);
        ACC4(u0);
    }
#undef ACC4

    float inv = 1.f / fmaxf((float)(s1 - s0), 1.f);
    uint2 uo = *(const uint2*)(g_t2 + (size_t)node * 128 + 64 + hl * 4);
    float2 o0 = __half22float2(*(__half2*)&uo.x);
    float2 o1 = __half22float2(*(__half2*)&uo.y);
    float4 bb = *(const float4*)(b2 + hl * 4);
    float4 v;
    v.x = acc[0] * inv + o0.x + bb.x;
    v.y = acc[1] * inv + o0.y + bb.y;
    v.z = acc[2] * inv + o1.x + bb.z;
    v.w = acc[3] * inv + o1.y + bb.w;
    *(float4*)(out + (size_t)node * 64 + hl * 4) = v;
}

// ---------------- launch --------------------------------------------------------
extern "C" void kernel_launch(void* const* d_in, const int* in_sizes, int n_in,
                              void* d_out, int out_size) {
    const float* x   = (const float*)d_in[0];
    const int*   ei  = (const int*)d_in[1];      // staged int32 (verified empirically)
    const float* W1l = (const float*)d_in[2];
    const float* b1  = (const float*)d_in[3];
    const float* W1r = (const float*)d_in[4];
    const float* W2l = (const float*)d_in[5];
    const float* b2  = (const float*)d_in[6];
    const float* W2r = (const float*)d_in[7];
    float*       out = (float*)d_out;

    const int Nn = in_sizes[0] / 128;
    const int E  = in_sizes[1] / 2;
    const int nb = (Nn + 511) / 512;

    const int SMEM = 4 * TILE_BYTES;   // 73728
    cudaFuncSetAttribute(mma_kernel<1>, cudaFuncAttributeMaxDynamicSharedMemorySize, SMEM);
    cudaFuncSetAttribute(mma_kernel<2>, cudaFuncAttributeMaxDynamicSharedMemorySize, SMEM);

    const int EB = ((E + 255) / 256) * 256;
    const int prepThreads = EB + 98304 + Nn * 32;
    prep_kernel<<<(prepThreads + 255) / 256, 256>>>(ei, E, Nn, W1l, W1r, W2l, W2r, x);
    scan_kernel<<<nb, 512>>>(Nn, E);
    fill_kernel<<<(E + 255) / 256, 256>>>(E);
    agg1_kernel<<<(Nn * 16 + 255) / 256, 256>>>(Nn);

    const int grid = (Nn + 127) / 128;
    mma_kernel<1><<<dim3(grid, 2), 256, SMEM>>>(b1, Nn);
    mma_kernel<2><<<dim3(grid, 1), 256, SMEM>>>(b2, Nn);
    agg2_final_kernel<<<(Nn * 16 + 255) / 256, 256>>>(b2, out, Nn);
}

// round 15
// speedup vs baseline: 1.0865x; 1.0794x over previous
#include <cuda_runtime.h>
#include <cuda_fp16.h>
#include <cstdint>

#define N_MAX 100000
#define N_PAD 100096
#define E_MAX 400000

// ---------------- scratch ---------------------------------------------------
__device__ __align__(16) __half g_a1[(size_t)N_PAD * 256];   // [agg1|x] fp16
__device__ __align__(16) __half g_t2[(size_t)N_MAX * 128];   // [t | o2] fp16
__device__ __align__(16) __half g_W1[256 * 256];             // [n][k]
__device__ __align__(16) __half g_W2[128 * 256];             // [n][k], n=[W2l|W2r]
__device__ int g_src[E_MAX], g_dst[E_MAX];
__device__ int g_cnt[N_MAX];            // zeroed by scan for next replay
__device__ int g_rowptr[N_MAX + 1], g_cursor[N_MAX], g_esrc[E_MAX];
__device__ volatile int g_flag[256];    // lookback status; zeroed by fill for next replay
__device__ volatile int g_bsum[256];
__device__ volatile int g_bpre[256];

// ---------------- helpers ---------------------------------------------------
__device__ __forceinline__ uint32_t smem_u32(const void* p) {
    uint32_t a;
    asm("{ .reg .u64 t; cvta.to.shared.u64 t, %1; cvt.u32.u64 %0, t; }" : "=r"(a) : "l"(p));
    return a;
}

__device__ __forceinline__ void cp16(uint32_t dst, const void* src) {
    asm volatile("cp.async.cg.shared.global [%0], [%1], 16;" :: "r"(dst), "l"(src) : "memory");
}
__device__ __forceinline__ void cp_commit() {
    asm volatile("cp.async.commit_group;" ::: "memory");
}
__device__ __forceinline__ void cp_wait0() {
    asm volatile("cp.async.wait_group 0;" ::: "memory");
}

__device__ __forceinline__ void ldsm_x4(uint32_t& r0, uint32_t& r1, uint32_t& r2, uint32_t& r3,
                                        uint32_t addr) {
    asm volatile("ldmatrix.sync.aligned.m8n8.x4.shared.b16 {%0,%1,%2,%3}, [%4];"
                 : "=r"(r0), "=r"(r1), "=r"(r2), "=r"(r3) : "r"(addr));
}

__device__ __forceinline__ void mma_f16(float* c, const uint32_t* a, uint32_t b0, uint32_t b1) {
    asm volatile(
        "mma.sync.aligned.m16n8k16.row.col.f32.f16.f16.f32 "
        "{%0,%1,%2,%3}, {%4,%5,%6,%7}, {%8,%9}, {%0,%1,%2,%3};"
        : "+f"(c[0]), "+f"(c[1]), "+f"(c[2]), "+f"(c[3])
        : "r"(a[0]), "r"(a[1]), "r"(a[2]), "r"(a[3]), "r"(b0), "r"(b1));
}

// ---------------- L1: convert edges (int32) + histogram + fp16 conversions ----
__global__ void prep_kernel(const int* __restrict__ ei, int E, int Nn,
                            const float* __restrict__ W1l, const float* __restrict__ W1r,
                            const float* __restrict__ W2l, const float* __restrict__ W2r,
                            const float* __restrict__ x) {
    const int EB = ((E + 255) / 256) * 256;
    int gid = blockIdx.x * 256 + threadIdx.x;
    if (gid < EB) {
        int e = gid;
        if (e < E) {
            int s = ei[e], d = ei[E + e];
            if (s < 0) s = 0; if (s >= Nn) s = Nn - 1;
            if (d < 0) d = 0; if (d >= Nn) d = Nn - 1;
            g_src[e] = s;
            g_dst[e] = d;
            atomicAdd(&g_cnt[d], 1);
        }
        return;
    }
    int g = gid - EB;
    if (g < 65536) {                         // W1 transposed
        int n = g & 255, k = g >> 8;
        float v = (k < 128) ? W1l[(size_t)k * 256 + n] : W1r[(size_t)(k - 128) * 256 + n];
        g_W1[n * 256 + k] = __float2half_rn(v);
    } else if (g < 98304) {                  // W2, n = [W2l|W2r]
        int q = g - 65536;
        int n = q & 127, k = q >> 7;
        float v = (n < 64) ? W2l[(size_t)k * 64 + n] : W2r[(size_t)k * 64 + (n - 64)];
        g_W2[n * 256 + k] = __float2half_rn(v);
    } else {                                 // x -> fp16, cols 128..255 of A1
        int q = g - 98304;
        if (q >= Nn * 32) return;
        int node = q >> 5;
        int c = (q & 31) * 4;
        float4 v = *(const float4*)(x + (size_t)node * 128 + c);
        __half2 p0 = __floats2half2_rn(v.x, v.y);
        __half2 p1 = __floats2half2_rn(v.z, v.w);
        *(uint2*)(g_a1 + (size_t)node * 256 + 128 + c) =
            make_uint2(*(uint32_t*)&p0, *(uint32_t*)&p1);
    }
}

// ---------------- L2: single-kernel decoupled-lookback scan -------------------
__global__ void scan_kernel(int Nn, int E) {
    __shared__ int s[512];
    __shared__ int s_off;
    const int bid = blockIdx.x;
    const int i = bid * 512 + threadIdx.x;
    int v = (i < Nn) ? g_cnt[i] : 0;
    s[threadIdx.x] = v;
    __syncthreads();
#pragma unroll
    for (int off = 1; off < 512; off <<= 1) {
        int t = (threadIdx.x >= off) ? s[threadIdx.x - off] : 0;
        __syncthreads();
        s[threadIdx.x] += t;
        __syncthreads();
    }
    if (threadIdx.x == 0) {
        int total = s[511];
        g_bsum[bid] = total;
        __threadfence();
        g_flag[bid] = 1;
        int excl = 0;
        for (int j = bid - 1; j >= 0; j--) {
            int f;
            do { f = g_flag[j]; } while (f == 0);
            if (f == 2) { excl += g_bpre[j]; break; }
            excl += g_bsum[j];
        }
        g_bpre[bid] = excl + total;
        __threadfence();
        g_flag[bid] = 2;
        s_off = excl;
    }
    __syncthreads();
    if (i < Nn) {
        int r = s[threadIdx.x] - v + s_off;
        g_rowptr[i] = r;
        g_cursor[i] = r;
        g_cnt[i] = 0;                        // ready for next replay
    }
    if (i == 0) g_rowptr[Nn] = E;
}

// ---------------- L3: fill CSR (+ reset lookback flags) -----------------------
__global__ void fill_kernel(int E) {
    int e = blockIdx.x * blockDim.x + threadIdx.x;
    if (e < 256) g_flag[e] = 0;
    if (e < E) {
        int pos = atomicAdd(&g_cursor[g_dst[e]], 1);
        g_esrc[pos] = g_src[e];
    }
}

// ---------------- L4: agg1 — 2 nodes/warp, 4-deep pipelined gather ------------
__global__ void agg1_kernel(int Nn) {
    int gw = (blockIdx.x * blockDim.x + threadIdx.x) >> 5;
    int lane = threadIdx.x & 31;
    int node = gw * 2 + (lane >> 4);
    int hl = lane & 15;
    if (node >= Nn) return;
    int s0 = g_rowptr[node], s1 = g_rowptr[node + 1];
    float acc[8] = {0.f, 0.f, 0.f, 0.f, 0.f, 0.f, 0.f, 0.f};
    const __half* base = g_a1 + 128 + hl * 8;

    int e = s0;
    for (; e + 3 < s1; e += 4) {
        int i0 = g_esrc[e], i1 = g_esrc[e + 1], i2 = g_esrc[e + 2], i3 = g_esrc[e + 3];
        uint4 u0 = *(const uint4*)(base + (size_t)i0 * 256);
        uint4 u1 = *(const uint4*)(base + (size_t)i1 * 256);
        uint4 u2 = *(const uint4*)(base + (size_t)i2 * 256);
        uint4 u3 = *(const uint4*)(base + (size_t)i3 * 256);
#define ACC8(U) do { \
        float2 f0 = __half22float2(*(__half2*)&(U).x); \
        float2 f1 = __half22float2(*(__half2*)&(U).y); \
        float2 f2 = __half22float2(*(__half2*)&(U).z); \
        float2 f3 = __half22float2(*(__half2*)&(U).w); \
        acc[0] += f0.x; acc[1] += f0.y; acc[2] += f1.x; acc[3] += f1.y; \
        acc[4] += f2.x; acc[5] += f2.y; acc[6] += f3.x; acc[7] += f3.y; } while (0)
        ACC8(u0); ACC8(u1); ACC8(u2); ACC8(u3);
    }
    for (; e < s1; e++) {
        int i0 = g_esrc[e];
        uint4 u0 = *(const uint4*)(base + (size_t)i0 * 256);
        ACC8(u0);
    }
#undef ACC8

    float inv = 1.f / fmaxf((float)(s1 - s0), 1.f);
    __half2 p0 = __floats2half2_rn(acc[0] * inv, acc[1] * inv);
    __half2 p1 = __floats2half2_rn(acc[2] * inv, acc[3] * inv);
    __half2 p2 = __floats2half2_rn(acc[4] * inv, acc[5] * inv);
    __half2 p3 = __floats2half2_rn(acc[6] * inv, acc[7] * inv);
    uint4 o;
    o.x = *(uint32_t*)&p0; o.y = *(uint32_t*)&p1;
    o.z = *(uint32_t*)&p2; o.w = *(uint32_t*)&p3;
    *(uint4*)(g_a1 + (size_t)node * 256 + hl * 8) = o;
}

// ---------------- L5: FUSED GEMM1+GEMM2, A-strip resident, occ 2 ---------------
// SMEM: AS = A strip 128x256 fp16, 528B rows (67584B); 2 B buffers 144B rows.
// Phase 1: h = relu(A @ W1 + b1), two n-halves over resident A; h -> AS in place.
// Phase 2: t2 = h @ W2 from SMEM; W2 chunks via B buffers.
#define HROW 528
#define AS_BYTES (128 * HROW)           // 67584
#define BT (128 * 144)                  // 18432
#define SMEM_F (AS_BYTES + 2 * BT)      // 104448

__global__ __launch_bounds__(256, 2)
void fused_kernel(const float* __restrict__ b1, int Nn) {
    extern __shared__ char sm[];
    const uint32_t smb = smem_u32(sm);
    const uint32_t AS = smb;
    const uint32_t Bb[2] = { smb + AS_BYTES, smb + AS_BYTES + BT };

    const int tid = threadIdx.x;
    const int wid = tid >> 5;
    const int lane = tid & 31;
    const int m0 = blockIdx.x * 128;

    const int wm = (wid >> 2) * 64;
    const int wn = (wid & 3) * 32;
    const int lrow = lane & 15;
    const int lcol8 = (lane >> 4) * 8;

    auto loadB = [&](uint32_t sB, const __half* W, int row0, int k0) {
        int row = tid >> 1;
        const char* src = (const char*)(W + (size_t)(row0 + row) * 256 + k0) + (tid & 1) * 64;
        uint32_t d = sB + row * 144 + (tid & 1) * 64;
#pragma unroll
        for (int j = 0; j < 4; j++) cp16(d + j * 16, src + j * 16);
    };

    // ---- prologue: A strip + first W1 chunk ----
    {
        int row = tid >> 1;
        const char* src = (const char*)(g_a1 + (size_t)(m0 + row) * 256) + (tid & 1) * 256;
        uint32_t d = AS + row * HROW + (tid & 1) * 256;
#pragma unroll
        for (int j = 0; j < 16; j++) cp16(d + j * 16, src + j * 16);
    }
    loadB(Bb[0], g_W1, 0, 0);
    cp_commit();
    cp_wait0();
    __syncthreads();

    float acc[4][4][4];
#pragma unroll
    for (int i = 0; i < 4; i++)
#pragma unroll
        for (int j = 0; j < 4; j++)
#pragma unroll
            for (int q = 0; q < 4; q++) acc[i][j][q] = 0.f;

    uint32_t hpack[32];                      // half-0 h (fp16 pairs), cold across half 1

    // ---- phase 1: 8 steps = 2 n-halves x 4 k-chunks ----
    for (int s = 0; s < 8; s++) {
        int c = s & 3;
        if (s + 1 < 8) {
            int h2 = (s + 1) >> 2, c2 = (s + 1) & 3;
            loadB(Bb[(s + 1) & 1], g_W1, h2 * 128, c2 * 64);
            cp_commit();
        }
        uint32_t sB = Bb[s & 1];
#pragma unroll
        for (int ks = 0; ks < 4; ks++) {
            int kbA = c * 64 + ks * 16 + lcol8;     // global k in A strip
            int kbB = ks * 16 + lcol8;              // local k in B chunk
            uint32_t a[4][4], b[2][4];
#pragma unroll
            for (int mt = 0; mt < 4; mt++)
                ldsm_x4(a[mt][0], a[mt][1], a[mt][2], a[mt][3],
                        AS + (wm + mt * 16 + lrow) * HROW + kbA * 2);
#pragma unroll
            for (int p = 0; p < 2; p++)
                ldsm_x4(b[p][0], b[p][1], b[p][2], b[p][3],
                        sB + (wn + p * 16 + lrow) * 144 + kbB * 2);
#pragma unroll
            for (int mt = 0; mt < 4; mt++)
#pragma unroll
                for (int nt = 0; nt < 4; nt++)
                    mma_f16(acc[mt][nt], a[mt], b[nt >> 1][nt & 1], b[nt >> 1][(nt & 1) + 2]);
        }
        if (s == 3) {
            // pack half 0 (cols wn.. in [0,128)) with bias+relu; reset acc
#pragma unroll
            for (int mt = 0; mt < 4; mt++)
#pragma unroll
                for (int nt = 0; nt < 4; nt++) {
                    int col = wn + nt * 8 + (lane & 3) * 2;
                    float bb0 = __ldg(b1 + col), bb1 = __ldg(b1 + col + 1);
#pragma unroll
                    for (int h = 0; h < 2; h++) {
                        float v0 = fmaxf(acc[mt][nt][2 * h + 0] + bb0, 0.f);
                        float v1 = fmaxf(acc[mt][nt][2 * h + 1] + bb1, 0.f);
                        __half2 p = __floats2half2_rn(v0, v1);
                        hpack[(mt * 4 + nt) * 2 + h] = *(uint32_t*)&p;
                        acc[mt][nt][2 * h + 0] = 0.f;
                        acc[mt][nt][2 * h + 1] = 0.f;
                    }
                }
        }
        if (s + 1 < 8) {
            cp_wait0();
            __syncthreads();
        }
    }
    __syncthreads();                         // all warps done reading A strip

    // ---- write h into AS (overwrites A) ----
#pragma unroll
    for (int mt = 0; mt < 4; mt++)
#pragma unroll
        for (int nt = 0; nt < 4; nt++) {
            int col0 = wn + nt * 8 + (lane & 3) * 2;
            int col1 = 128 + col0;
            float bb0 = __ldg(b1 + col1), bb1 = __ldg(b1 + col1 + 1);
#pragma unroll
            for (int h = 0; h < 2; h++) {
                int row = wm + mt * 16 + (lane >> 2) + h * 8;
                *(uint32_t*)(sm + row * HROW + col0 * 2) = hpack[(mt * 4 + nt) * 2 + h];
                float v0 = fmaxf(acc[mt][nt][2 * h + 0] + bb0, 0.f);
                float v1 = fmaxf(acc[mt][nt][2 * h + 1] + bb1, 0.f);
                __half2 p = __floats2half2_rn(v0, v1);
                *(uint32_t*)(sm + row * HROW + col1 * 2) = *(uint32_t*)&p;
            }
        }
    __syncthreads();

    // ---- phase 2: t2 = h @ W2 ----
#pragma unroll
    for (int i = 0; i < 4; i++)
#pragma unroll
        for (int j = 0; j < 4; j++)
#pragma unroll
            for (int q = 0; q < 4; q++) acc[i][j][q] = 0.f;

    loadB(Bb[0], g_W2, 0, 0);
    cp_commit();
    cp_wait0();
    __syncthreads();

    for (int s = 0; s < 4; s++) {
        if (s + 1 < 4) {
            loadB(Bb[(s + 1) & 1], g_W2, 0, (s + 1) * 64);
            cp_commit();
        }
        uint32_t sB = Bb[s & 1];
#pragma unroll
        for (int ks = 0; ks < 4; ks++) {
            int kbA = s * 64 + ks * 16 + lcol8;
            int kbB = ks * 16 + lcol8;
            uint32_t a[4][4], b[2][4];
#pragma unroll
            for (int mt = 0; mt < 4; mt++)
                ldsm_x4(a[mt][0], a[mt][1], a[mt][2], a[mt][3],
                        AS + (wm + mt * 16 + lrow) * HROW + kbA * 2);
#pragma unroll
            for (int p = 0; p < 2; p++)
                ldsm_x4(b[p][0], b[p][1], b[p][2], b[p][3],
                        sB + (wn + p * 16 + lrow) * 144 + kbB * 2);
#pragma unroll
            for (int mt = 0; mt < 4; mt++)
#pragma unroll
                for (int nt = 0; nt < 4; nt++)
                    mma_f16(acc[mt][nt], a[mt], b[nt >> 1][nt & 1], b[nt >> 1][(nt & 1) + 2]);
        }
        if (s + 1 < 4) {
            cp_wait0();
            __syncthreads();
        }
    }

    // ---- epilogue: write g_t2 ----
#pragma unroll
    for (int mt = 0; mt < 4; mt++) {
        int r0 = m0 + wm + mt * 16 + (lane >> 2);
#pragma unroll
        for (int nt = 0; nt < 4; nt++) {
            int colL = wn + nt * 8 + (lane & 3) * 2;
#pragma unroll
            for (int h = 0; h < 2; h++) {
                int r = r0 + h * 8;
                if (r < Nn) {
                    __half2 p = __floats2half2_rn(acc[mt][nt][2 * h + 0],
                                                  acc[mt][nt][2 * h + 1]);
                    *(uint32_t*)(g_t2 + (size_t)r * 128 + colL) = *(uint32_t*)&p;
                }
            }
        }
    }
}

// ---------------- L6: agg2 + final — 2 nodes/warp, 4-deep pipelined gather ----
__global__ void agg2_final_kernel(const float* __restrict__ b2,
                                  float* __restrict__ out, int Nn) {
    int gw = (blockIdx.x * blockDim.x + threadIdx.x) >> 5;
    int lane = threadIdx.x & 31;
    int node = gw * 2 + (lane >> 4);
    int hl = lane & 15;
    if (node >= Nn) return;
    int s0 = g_rowptr[node], s1 = g_rowptr[node + 1];
    float acc[4] = {0.f, 0.f, 0.f, 0.f};
    const __half* base = g_t2 + hl * 4;

    int e = s0;
    for (; e + 3 < s1; e += 4) {
        int i0 = g_esrc[e], i1 = g_esrc[e + 1], i2 = g_esrc[e + 2], i3 = g_esrc[e + 3];
        uint2 u0 = *(const uint2*)(base + (size_t)i0 * 128);
        uint2 u1 = *(const uint2*)(base + (size_t)i1 * 128);
        uint2 u2 = *(const uint2*)(base + (size_t)i2 * 128);
        uint2 u3 = *(const uint2*)(base + (size_t)i3 * 128);
#define ACC4(U) do { \
        float2 f0 = __half22float2(*(__half2*)&(U).x); \
        float2 f1 = __half22float2(*(__half2*)&(U).y); \
        acc[0] += f0.x; acc[1] += f0.y; acc[2] += f1.x; acc[3] += f1.y; } while (0)
        ACC4(u0); ACC4(u1); ACC4(u2); ACC4(u3);
    }
    for (; e < s1; e++) {
        int i0 = g_esrc[e];
        uint2 u0 = *(const uint2*)(base + (size_t)i0 * 128);
        ACC4(u0);
    }
#undef ACC4

    float inv = 1.f / fmaxf((float)(s1 - s0), 1.f);
    uint2 uo = *(const uint2*)(g_t2 + (size_t)node * 128 + 64 + hl * 4);
    float2 o0 = __half22float2(*(__half2*)&uo.x);
    float2 o1 = __half22float2(*(__half2*)&uo.y);
    float4 bb = *(const float4*)(b2 + hl * 4);
    float4 v;
    v.x = acc[0] * inv + o0.x + bb.x;
    v.y = acc[1] * inv + o0.y + bb.y;
    v.z = acc[2] * inv + o1.x + bb.z;
    v.w = acc[3] * inv + o1.y + bb.w;
    *(float4*)(out + (size_t)node * 64 + hl * 4) = v;
}

// ---------------- launch --------------------------------------------------------
extern "C" void kernel_launch(void* const* d_in, const int* in_sizes, int n_in,
                              void* d_out, int out_size) {
    const float* x   = (const float*)d_in[0];
    const int*   ei  = (const int*)d_in[1];      // staged int32 (verified empirically)
    const float* W1l = (const float*)d_in[2];
    const float* b1  = (const float*)d_in[3];
    const float* W1r = (const float*)d_in[4];
    const float* W2l = (const float*)d_in[5];
    const float* b2  = (const float*)d_in[6];
    const float* W2r = (const float*)d_in[7];
    float*       out = (float*)d_out;

    const int Nn = in_sizes[0] / 128;
    const int E  = in_sizes[1] / 2;
    const int nb = (Nn + 511) / 512;

    cudaFuncSetAttribute(fused_kernel,
                         cudaFuncAttributeMaxDynamicSharedMemorySize, SMEM_F);

    const int EB = ((E + 255) / 256) * 256;
    const int prepThreads = EB + 98304 + Nn * 32;
    prep_kernel<<<(prepThreads + 255) / 256, 256>>>(ei, E, Nn, W1l, W1r, W2l, W2r, x);
    scan_kernel<<<nb, 512>>>(Nn, E);
    fill_kernel<<<(E + 255) / 256, 256>>>(E);
    agg1_kernel<<<(Nn * 16 + 255) / 256, 256>>>(Nn);

    fused_kernel<<<(Nn + 127) / 128, 256, SMEM_F>>>(b1, Nn);

    agg2_final_kernel<<<(Nn * 16 + 255) / 256, 256>>>(b2, out, Nn);
}

// round 16
// speedup vs baseline: 1.1261x; 1.0365x over previous
#include <cuda_runtime.h>
#include <cuda_fp16.h>
#include <cstdint>

#define N_MAX 100000
#define N_PAD 100096
#define E_MAX 400000

// ---------------- scratch ---------------------------------------------------
__device__ __align__(16) __half g_x16[(size_t)N_PAD * 128];  // x fp16 (256B rows)
__device__ __align__(16) __half g_t2[(size_t)N_MAX * 128];   // [t | o2] fp16
__device__ __align__(16) __half g_W1[256 * 256];             // [n][k]
__device__ __align__(16) __half g_W2[128 * 256];             // [n][k], n=[W2l|W2r]
__device__ int g_src[E_MAX], g_dst[E_MAX];
__device__ int g_cnt[N_MAX];            // zeroed by scan for next replay
__device__ int g_rowptr[N_MAX + 1], g_cursor[N_MAX], g_esrc[E_MAX];
__device__ volatile int g_flag[256];    // lookback status; zeroed by fill for next replay
__device__ volatile int g_bsum[256];
__device__ volatile int g_bpre[256];

// ---------------- helpers ---------------------------------------------------
__device__ __forceinline__ uint32_t smem_u32(const void* p) {
    uint32_t a;
    asm("{ .reg .u64 t; cvta.to.shared.u64 t, %1; cvt.u32.u64 %0, t; }" : "=r"(a) : "l"(p));
    return a;
}

__device__ __forceinline__ void cp16(uint32_t dst, const void* src) {
    asm volatile("cp.async.cg.shared.global [%0], [%1], 16;" :: "r"(dst), "l"(src) : "memory");
}
__device__ __forceinline__ void cp_commit() {
    asm volatile("cp.async.commit_group;" ::: "memory");
}
__device__ __forceinline__ void cp_wait0() {
    asm volatile("cp.async.wait_group 0;" ::: "memory");
}

__device__ __forceinline__ void ldsm_x4(uint32_t& r0, uint32_t& r1, uint32_t& r2, uint32_t& r3,
                                        uint32_t addr) {
    asm volatile("ldmatrix.sync.aligned.m8n8.x4.shared.b16 {%0,%1,%2,%3}, [%4];"
                 : "=r"(r0), "=r"(r1), "=r"(r2), "=r"(r3) : "r"(addr));
}

__device__ __forceinline__ void mma_f16(float* c, const uint32_t* a, uint32_t b0, uint32_t b1) {
    asm volatile(
        "mma.sync.aligned.m16n8k16.row.col.f32.f16.f16.f32 "
        "{%0,%1,%2,%3}, {%4,%5,%6,%7}, {%8,%9}, {%0,%1,%2,%3};"
        : "+f"(c[0]), "+f"(c[1]), "+f"(c[2]), "+f"(c[3])
        : "r"(a[0]), "r"(a[1]), "r"(a[2]), "r"(a[3]), "r"(b0), "r"(b1));
}

// ---------------- L1: convert edges (int32) + histogram + fp16 conversions ----
__global__ void prep_kernel(const int* __restrict__ ei, int E, int Nn,
                            const float* __restrict__ W1l, const float* __restrict__ W1r,
                            const float* __restrict__ W2l, const float* __restrict__ W2r,
                            const float* __restrict__ x) {
    const int EB = ((E + 255) / 256) * 256;
    int gid = blockIdx.x * 256 + threadIdx.x;
    if (gid < EB) {
        int e = gid;
        if (e < E) {
            int s = ei[e], d = ei[E + e];
            if (s < 0) s = 0; if (s >= Nn) s = Nn - 1;
            if (d < 0) d = 0; if (d >= Nn) d = Nn - 1;
            g_src[e] = s;
            g_dst[e] = d;
            atomicAdd(&g_cnt[d], 1);
        }
        return;
    }
    int g = gid - EB;
    if (g < 65536) {                         // W1 transposed
        int n = g & 255, k = g >> 8;
        float v = (k < 128) ? W1l[(size_t)k * 256 + n] : W1r[(size_t)(k - 128) * 256 + n];
        g_W1[n * 256 + k] = __float2half_rn(v);
    } else if (g < 98304) {                  // W2, n = [W2l|W2r]
        int q = g - 65536;
        int n = q & 127, k = q >> 7;
        float v = (n < 64) ? W2l[(size_t)k * 64 + n] : W2r[(size_t)k * 64 + (n - 64)];
        g_W2[n * 256 + k] = __float2half_rn(v);
    } else {                                 // x -> fp16 rows
        int q = g - 98304;
        if (q >= Nn * 32) return;
        int node = q >> 5;
        int c = (q & 31) * 4;
        float4 v = *(const float4*)(x + (size_t)node * 128 + c);
        __half2 p0 = __floats2half2_rn(v.x, v.y);
        __half2 p1 = __floats2half2_rn(v.z, v.w);
        *(uint2*)(g_x16 + (size_t)node * 128 + c) =
            make_uint2(*(uint32_t*)&p0, *(uint32_t*)&p1);
    }
}

// ---------------- L2: single-kernel decoupled-lookback scan -------------------
__global__ void scan_kernel(int Nn, int E) {
    __shared__ int s[512];
    __shared__ int s_off;
    const int bid = blockIdx.x;
    const int i = bid * 512 + threadIdx.x;
    int v = (i < Nn) ? g_cnt[i] : 0;
    s[threadIdx.x] = v;
    __syncthreads();
#pragma unroll
    for (int off = 1; off < 512; off <<= 1) {
        int t = (threadIdx.x >= off) ? s[threadIdx.x - off] : 0;
        __syncthreads();
        s[threadIdx.x] += t;
        __syncthreads();
    }
    if (threadIdx.x == 0) {
        int total = s[511];
        g_bsum[bid] = total;
        __threadfence();
        g_flag[bid] = 1;
        int excl = 0;
        for (int j = bid - 1; j >= 0; j--) {
            int f;
            do { f = g_flag[j]; } while (f == 0);
            if (f == 2) { excl += g_bpre[j]; break; }
            excl += g_bsum[j];
        }
        g_bpre[bid] = excl + total;
        __threadfence();
        g_flag[bid] = 2;
        s_off = excl;
    }
    __syncthreads();
    if (i < Nn) {
        int r = s[threadIdx.x] - v + s_off;
        g_rowptr[i] = r;
        g_cursor[i] = r;
        g_cnt[i] = 0;                        // ready for next replay
    }
    if (i == 0) g_rowptr[Nn] = E;
}

// ---------------- L3: fill CSR (+ reset lookback flags) -----------------------
__global__ void fill_kernel(int E) {
    int e = blockIdx.x * blockDim.x + threadIdx.x;
    if (e < 256) g_flag[e] = 0;
    if (e < E) {
        int pos = atomicAdd(&g_cursor[g_dst[e]], 1);
        g_esrc[pos] = g_src[e];
    }
}

// ---------------- L4: FUSED gather + GEMM1 + GEMM2 -----------------------------
// SMEM: AS = A strip 128x256 fp16, 528B rows; 2 B buffers 144B rows.
// Prologue: gather-mean(x[neigh]) -> AS cols 0-127 (LDG, overlaps cp.async of
//           own-x -> cols 128-255 and first W1 chunk).
// Phase 1:  h = relu(A @ W1 + b1) over resident A; h -> AS in place.
// Phase 2:  t2 = h @ W2 from SMEM.
#define HROW 528
#define AS_BYTES (128 * HROW)           // 67584
#define BT (128 * 144)                  // 18432
#define SMEM_F (AS_BYTES + 2 * BT)      // 104448

__global__ __launch_bounds__(256, 2)
void fused_kernel(const float* __restrict__ b1, int Nn) {
    extern __shared__ char sm[];
    const uint32_t smb = smem_u32(sm);
    const uint32_t AS = smb;
    const uint32_t Bb[2] = { smb + AS_BYTES, smb + AS_BYTES + BT };

    const int tid = threadIdx.x;
    const int wid = tid >> 5;
    const int lane = tid & 31;
    const int m0 = blockIdx.x * 128;

    const int wm = (wid >> 2) * 64;
    const int wn = (wid & 3) * 32;
    const int lrow = lane & 15;
    const int lcol8 = (lane >> 4) * 8;

    auto loadB = [&](uint32_t sB, const __half* W, int row0, int k0) {
        int row = tid >> 1;
        const char* src = (const char*)(W + (size_t)(row0 + row) * 256 + k0) + (tid & 1) * 64;
        uint32_t d = sB + row * 144 + (tid & 1) * 64;
#pragma unroll
        for (int j = 0; j < 4; j++) cp16(d + j * 16, src + j * 16);
    };

    // ---- async: own-x -> AS cols 128-255, + first W1 chunk ----
    {
        int row = tid >> 1;
        const char* src = (const char*)(g_x16 + (size_t)(m0 + row) * 128) + (tid & 1) * 128;
        uint32_t d = AS + row * HROW + 256 + (tid & 1) * 128;
#pragma unroll
        for (int j = 0; j < 8; j++) cp16(d + j * 16, src + j * 16);
    }
    loadB(Bb[0], g_W1, 0, 0);
    cp_commit();

    // ---- gather-mean -> AS cols 0-127 (overlaps the cp.async above) ----
    // 4 threads per row; each covers 32 fp16 (64B). 2 passes of 64 rows.
#pragma unroll
    for (int pass = 0; pass < 2; pass++) {
        int rl = pass * 64 + (tid >> 2);
        int q = tid & 3;
        int node = m0 + rl;
        float acc[32];
#pragma unroll
        for (int j = 0; j < 32; j++) acc[j] = 0.f;
        if (node < Nn) {
            int s0 = g_rowptr[node], s1 = g_rowptr[node + 1];
            const __half* base = g_x16 + q * 32;
            for (int e = s0; e < s1; e++) {
                int src = g_esrc[e];
                const uint4* p = (const uint4*)(base + (size_t)src * 128);
                uint4 u0 = p[0], u1 = p[1], u2 = p[2], u3 = p[3];
#define A8(U, o) do { \
                float2 f0 = __half22float2(*(__half2*)&(U).x); \
                float2 f1 = __half22float2(*(__half2*)&(U).y); \
                float2 f2 = __half22float2(*(__half2*)&(U).z); \
                float2 f3 = __half22float2(*(__half2*)&(U).w); \
                acc[(o)+0] += f0.x; acc[(o)+1] += f0.y; acc[(o)+2] += f1.x; acc[(o)+3] += f1.y; \
                acc[(o)+4] += f2.x; acc[(o)+5] += f2.y; acc[(o)+6] += f3.x; acc[(o)+7] += f3.y; } while (0)
                A8(u0, 0); A8(u1, 8); A8(u2, 16); A8(u3, 24);
#undef A8
            }
            float inv = 1.f / fmaxf((float)(s1 - s0), 1.f);
#pragma unroll
            for (int j = 0; j < 32; j++) acc[j] *= inv;
        }
        uint32_t pk[16];
#pragma unroll
        for (int j = 0; j < 16; j++) {
            __half2 p = __floats2half2_rn(acc[2 * j], acc[2 * j + 1]);
            pk[j] = *(uint32_t*)&p;
        }
        char* dst = sm + rl * HROW + q * 64;
#pragma unroll
        for (int v = 0; v < 4; v++) *(uint4*)(dst + v * 16) = ((uint4*)pk)[v];
    }

    cp_wait0();
    __syncthreads();

    float acc[4][4][4];
#pragma unroll
    for (int i = 0; i < 4; i++)
#pragma unroll
        for (int j = 0; j < 4; j++)
#pragma unroll
            for (int q = 0; q < 4; q++) acc[i][j][q] = 0.f;

    uint32_t hpack[32];                      // half-0 h (fp16 pairs), cold across half 1

    // ---- phase 1: 8 steps = 2 n-halves x 4 k-chunks ----
    for (int s = 0; s < 8; s++) {
        int c = s & 3;
        if (s + 1 < 8) {
            int h2 = (s + 1) >> 2, c2 = (s + 1) & 3;
            loadB(Bb[(s + 1) & 1], g_W1, h2 * 128, c2 * 64);
            cp_commit();
        }
        uint32_t sB = Bb[s & 1];
#pragma unroll
        for (int ks = 0; ks < 4; ks++) {
            int kbA = c * 64 + ks * 16 + lcol8;
            int kbB = ks * 16 + lcol8;
            uint32_t a[4][4], b[2][4];
#pragma unroll
            for (int mt = 0; mt < 4; mt++)
                ldsm_x4(a[mt][0], a[mt][1], a[mt][2], a[mt][3],
                        AS + (wm + mt * 16 + lrow) * HROW + kbA * 2);
#pragma unroll
            for (int p = 0; p < 2; p++)
                ldsm_x4(b[p][0], b[p][1], b[p][2], b[p][3],
                        sB + (wn + p * 16 + lrow) * 144 + kbB * 2);
#pragma unroll
            for (int mt = 0; mt < 4; mt++)
#pragma unroll
                for (int nt = 0; nt < 4; nt++)
                    mma_f16(acc[mt][nt], a[mt], b[nt >> 1][nt & 1], b[nt >> 1][(nt & 1) + 2]);
        }
        if (s == 3) {
#pragma unroll
            for (int mt = 0; mt < 4; mt++)
#pragma unroll
                for (int nt = 0; nt < 4; nt++) {
                    int col = wn + nt * 8 + (lane & 3) * 2;
                    float bb0 = __ldg(b1 + col), bb1 = __ldg(b1 + col + 1);
#pragma unroll
                    for (int h = 0; h < 2; h++) {
                        float v0 = fmaxf(acc[mt][nt][2 * h + 0] + bb0, 0.f);
                        float v1 = fmaxf(acc[mt][nt][2 * h + 1] + bb1, 0.f);
                        __half2 p = __floats2half2_rn(v0, v1);
                        hpack[(mt * 4 + nt) * 2 + h] = *(uint32_t*)&p;
                        acc[mt][nt][2 * h + 0] = 0.f;
                        acc[mt][nt][2 * h + 1] = 0.f;
                    }
                }
        }
        if (s + 1 < 8) {
            cp_wait0();
            __syncthreads();
        }
    }
    __syncthreads();                         // all warps done reading A strip

    // ---- write h into AS (overwrites A) ----
#pragma unroll
    for (int mt = 0; mt < 4; mt++)
#pragma unroll
        for (int nt = 0; nt < 4; nt++) {
            int col0 = wn + nt * 8 + (lane & 3) * 2;
            int col1 = 128 + col0;
            float bb0 = __ldg(b1 + col1), bb1 = __ldg(b1 + col1 + 1);
#pragma unroll
            for (int h = 0; h < 2; h++) {
                int row = wm + mt * 16 + (lane >> 2) + h * 8;
                *(uint32_t*)(sm + row * HROW + col0 * 2) = hpack[(mt * 4 + nt) * 2 + h];
                float v0 = fmaxf(acc[mt][nt][2 * h + 0] + bb0, 0.f);
                float v1 = fmaxf(acc[mt][nt][2 * h + 1] + bb1, 0.f);
                __half2 p = __floats2half2_rn(v0, v1);
                *(uint32_t*)(sm + row * HROW + col1 * 2) = *(uint32_t*)&p;
            }
        }
    __syncthreads();

    // ---- phase 2: t2 = h @ W2 ----
#pragma unroll
    for (int i = 0; i < 4; i++)
#pragma unroll
        for (int j = 0; j < 4; j++)
#pragma unroll
            for (int q = 0; q < 4; q++) acc[i][j][q] = 0.f;

    loadB(Bb[0], g_W2, 0, 0);
    cp_commit();
    cp_wait0();
    __syncthreads();

    for (int s = 0; s < 4; s++) {
        if (s + 1 < 4) {
            loadB(Bb[(s + 1) & 1], g_W2, 0, (s + 1) * 64);
            cp_commit();
        }
        uint32_t sB = Bb[s & 1];
#pragma unroll
        for (int ks = 0; ks < 4; ks++) {
            int kbA = s * 64 + ks * 16 + lcol8;
            int kbB = ks * 16 + lcol8;
            uint32_t a[4][4], b[2][4];
#pragma unroll
            for (int mt = 0; mt < 4; mt++)
                ldsm_x4(a[mt][0], a[mt][1], a[mt][2], a[mt][3],
                        AS + (wm + mt * 16 + lrow) * HROW + kbA * 2);
#pragma unroll
            for (int p = 0; p < 2; p++)
                ldsm_x4(b[p][0], b[p][1], b[p][2], b[p][3],
                        sB + (wn + p * 16 + lrow) * 144 + kbB * 2);
#pragma unroll
            for (int mt = 0; mt < 4; mt++)
#pragma unroll
                for (int nt = 0; nt < 4; nt++)
                    mma_f16(acc[mt][nt], a[mt], b[nt >> 1][nt & 1], b[nt >> 1][(nt & 1) + 2]);
        }
        if (s + 1 < 4) {
            cp_wait0();
            __syncthreads();
        }
    }

    // ---- epilogue: write g_t2 ----
#pragma unroll
    for (int mt = 0; mt < 4; mt++) {
        int r0 = m0 + wm + mt * 16 + (lane >> 2);
#pragma unroll
        for (int nt = 0; nt < 4; nt++) {
            int colL = wn + nt * 8 + (lane & 3) * 2;
#pragma unroll
            for (int h = 0; h < 2; h++) {
                int r = r0 + h * 8;
                if (r < Nn) {
                    __half2 p = __floats2half2_rn(acc[mt][nt][2 * h + 0],
                                                  acc[mt][nt][2 * h + 1]);
                    *(uint32_t*)(g_t2 + (size_t)r * 128 + colL) = *(uint32_t*)&p;
                }
            }
        }
    }
}

// ---------------- L5: agg2 + final — 2 nodes/warp, 4-deep pipelined gather ----
__global__ void agg2_final_kernel(const float* __restrict__ b2,
                                  float* __restrict__ out, int Nn) {
    int gw = (blockIdx.x * blockDim.x + threadIdx.x) >> 5;
    int lane = threadIdx.x & 31;
    int node = gw * 2 + (lane >> 4);
    int hl = lane & 15;
    if (node >= Nn) return;
    int s0 = g_rowptr[node], s1 = g_rowptr[node + 1];
    float acc[4] = {0.f, 0.f, 0.f, 0.f};
    const __half* base = g_t2 + hl * 4;

    int e = s0;
    for (; e + 3 < s1; e += 4) {
        int i0 = g_esrc[e], i1 = g_esrc[e + 1], i2 = g_esrc[e + 2], i3 = g_esrc[e + 3];
        uint2 u0 = *(const uint2*)(base + (size_t)i0 * 128);
        uint2 u1 = *(const uint2*)(base + (size_t)i1 * 128);
        uint2 u2 = *(const uint2*)(base + (size_t)i2 * 128);
        uint2 u3 = *(const uint2*)(base + (size_t)i3 * 128);
#define ACC4(U) do { \
        float2 f0 = __half22float2(*(__half2*)&(U).x); \
        float2 f1 = __half22float2(*(__half2*)&(U).y); \
        acc[0] += f0.x; acc[1] += f0.y; acc[2] += f1.x; acc[3] += f1.y; } while (0)
        ACC4(u0); ACC4(u1); ACC4(u2); ACC4(u3);
    }
    for (; e < s1; e++) {
        int i0 = g_esrc[e];
        uint2 u0 = *(const uint2*)(base + (size_t)i0 * 128);
        ACC4(u0);
    }
#undef ACC4

    float inv = 1.f / fmaxf((float)(s1 - s0), 1.f);
    uint2 uo = *(const uint2*)(g_t2 + (size_t)node * 128 + 64 + hl * 4);
    float2 o0 = __half22float2(*(__half2*)&uo.x);
    float2 o1 = __half22float2(*(__half2*)&uo.y);
    float4 bb = *(const float4*)(b2 + hl * 4);
    float4 v;
    v.x = acc[0] * inv + o0.x + bb.x;
    v.y = acc[1] * inv + o0.y + bb.y;
    v.z = acc[2] * inv + o1.x + bb.z;
    v.w = acc[3] * inv + o1.y + bb.w;
    *(float4*)(out + (size_t)node * 64 + hl * 4) = v;
}

// ---------------- launch --------------------------------------------------------
extern "C" void kernel_launch(void* const* d_in, const int* in_sizes, int n_in,
                              void* d_out, int out_size) {
    const float* x   = (const float*)d_in[0];
    const int*   ei  = (const int*)d_in[1];      // staged int32 (verified empirically)
    const float* W1l = (const float*)d_in[2];
    const float* b1  = (const float*)d_in[3];
    const float* W1r = (const float*)d_in[4];
    const float* W2l = (const float*)d_in[5];
    const float* b2  = (const float*)d_in[6];
    const float* W2r = (const float*)d_in[7];
    float*       out = (float*)d_out;

    const int Nn = in_sizes[0] / 128;
    const int E  = in_sizes[1] / 2;
    const int nb = (Nn + 511) / 512;

    cudaFuncSetAttribute(fused_kernel,
                         cudaFuncAttributeMaxDynamicSharedMemorySize, SMEM_F);

    const int EB = ((E + 255) / 256) * 256;
    const int prepThreads = EB + 98304 + Nn * 32;
    prep_kernel<<<(prepThreads + 255) / 256, 256>>>(ei, E, Nn, W1l, W1r, W2l, W2r, x);
    scan_kernel<<<nb, 512>>>(Nn, E);
    fill_kernel<<<(E + 255) / 256, 256>>>(E);

    fused_kernel<<<(Nn + 127) / 128, 256, SMEM_F>>>(b1, Nn);

    agg2_final_kernel<<<(Nn * 16 + 255) / 256, 256>>>(b2, out, Nn);
}